// round 5
// baseline (speedup 1.0000x reference)
#include <cuda_runtime.h>

#define HID   512
#define S_LEN 4096
#define BATCH 2
#define NHEAD 8
#define DH    64
#define MROWS (BATCH * S_LEN)   /* 8192 */

/* -------- scratch (no allocations allowed) -------- */
__device__ float g_Q[MROWS * HID];
__device__ float g_K[MROWS * HID];
__device__ float g_V[MROWS * HID];
__device__ float g_C[MROWS * HID];

/* ================= projection GEMM : Y = X @ W^T + b =================
 * X: [M,K] row-major, W: [N,K] row-major (nn.Linear weight), Y: [M,512]
 * 128x128 tile, BK=8, 256 threads, 8x8 micro-tile. */
#define PM 128
#define PN 128
#define PK 8

__global__ void __launch_bounds__(256, 2) proj_gemm(
    const float* __restrict__ X, const float* __restrict__ W,
    const float* __restrict__ bias, float* __restrict__ Y, int Kdim)
{
    __shared__ float As[PK][PM];
    __shared__ float Bs[PK][PN];

    const int tid = threadIdx.x;
    const int tx = tid & 15;        /* col group */
    const int ty = tid >> 4;        /* row group */
    const int bm = blockIdx.x * PM;
    const int bn = blockIdx.y * PN;

    const int lrow = tid >> 1;          /* 0..127 */
    const int lcol = (tid & 1) * 4;     /* 0 or 4 */

    const float* Ap = X + (size_t)(bm + lrow) * Kdim + lcol;
    const float* Bp = W + (size_t)(bn + lrow) * Kdim + lcol;

    float acc[8][8];
#pragma unroll
    for (int i = 0; i < 8; i++)
#pragma unroll
        for (int j = 0; j < 8; j++) acc[i][j] = 0.f;

    for (int k0 = 0; k0 < Kdim; k0 += PK) {
        float4 a4 = *(const float4*)(Ap + k0);
        float4 b4 = *(const float4*)(Bp + k0);
        __syncthreads();                 /* previous iter consumers done */
        As[lcol + 0][lrow] = a4.x;
        As[lcol + 1][lrow] = a4.y;
        As[lcol + 2][lrow] = a4.z;
        As[lcol + 3][lrow] = a4.w;
        Bs[lcol + 0][lrow] = b4.x;
        Bs[lcol + 1][lrow] = b4.y;
        Bs[lcol + 2][lrow] = b4.z;
        Bs[lcol + 3][lrow] = b4.w;
        __syncthreads();
#pragma unroll
        for (int kk = 0; kk < PK; kk++) {
            float a[8], b[8];
            *(float4*)(a)     = *(const float4*)&As[kk][ty * 8];
            *(float4*)(a + 4) = *(const float4*)&As[kk][ty * 8 + 4];
            *(float4*)(b)     = *(const float4*)&Bs[kk][tx * 8];
            *(float4*)(b + 4) = *(const float4*)&Bs[kk][tx * 8 + 4];
#pragma unroll
            for (int i = 0; i < 8; i++)
#pragma unroll
                for (int j = 0; j < 8; j++)
                    acc[i][j] = fmaf(a[i], b[j], acc[i][j]);
        }
    }

    float bv[8];
#pragma unroll
    for (int j = 0; j < 8; j++) bv[j] = bias[bn + tx * 8 + j];

#pragma unroll
    for (int i = 0; i < 8; i++) {
        int row = bm + ty * 8 + i;
        float* yp = Y + (size_t)row * HID + bn + tx * 8;
        float4 r0, r1;
        r0.x = acc[i][0] + bv[0]; r0.y = acc[i][1] + bv[1];
        r0.z = acc[i][2] + bv[2]; r0.w = acc[i][3] + bv[3];
        r1.x = acc[i][4] + bv[4]; r1.y = acc[i][5] + bv[5];
        r1.z = acc[i][6] + bv[6]; r1.w = acc[i][7] + bv[7];
        *(float4*)yp       = r0;
        *(float4*)(yp + 4) = r1;
    }
}

/* ================= flash attention (fp32) =================
 * One block per (128-row q tile, head, batch). 256 threads.
 * Qt/Kt transposed [d][col] with XOR swizzle on bits 2..4 of col. */
#define BQ    128
#define BKEYS 128
#define PSP   132            /* Ps pitch */
#define NKT   (S_LEN / BKEYS)

#define ATTN_SMEM_FLOATS (64*128 + 64*128 + 128*DH + 128*PSP + 3*128)
#define ATTN_SMEM_BYTES  (ATTN_SMEM_FLOATS * 4)

__device__ __forceinline__ int att_swz(int d, int col) {
    return d * 128 + (col ^ (((d >> 2) & 7) << 2));
}

__global__ void __launch_bounds__(256, 1) attn_kernel(
    const float* __restrict__ Q, const float* __restrict__ K,
    const float* __restrict__ V, float* __restrict__ C)
{
    extern __shared__ float sm[];
    float* Qt  = sm;                    /* [64][128] swizzled, pre-scaled */
    float* Kt  = Qt + 64 * 128;         /* [64][128] swizzled */
    float* Vs  = Kt + 64 * 128;         /* [128][64] natural */
    float* Ps  = Vs + 128 * DH;         /* [128][PSP] */
    float* m_s = Ps + 128 * PSP;        /* running max per row */
    float* l_s = m_s + 128;             /* running sum per row */
    float* c_s = l_s + 128;             /* correction per row */

    const int tid = threadIdx.x;
    const int tx  = tid & 15, ty  = tid >> 4;   /* S-phase 16x16, 8x8 micro */
    const int otx = tid & 7,  oty = tid >> 3;   /* O-phase 32x8,  4x8 micro */

    const int qt = blockIdx.x, h = blockIdx.y, b = blockIdx.z;
    const size_t base = (size_t)b * S_LEN * HID + h * DH;

    /* load Q tile transposed + swizzled, pre-scaled by 1/sqrt(64)=0.125 */
    for (int i = tid; i < BQ * DH / 4; i += 256) {
        int row = i >> 4;
        int d   = (i & 15) << 2;
        float4 q4 = *(const float4*)(Q + base + (size_t)(qt * BQ + row) * HID + d);
        Qt[att_swz(d + 0, row)] = q4.x * 0.125f;
        Qt[att_swz(d + 1, row)] = q4.y * 0.125f;
        Qt[att_swz(d + 2, row)] = q4.z * 0.125f;
        Qt[att_swz(d + 3, row)] = q4.w * 0.125f;
    }
    for (int i = tid; i < BQ; i += 256) { m_s[i] = -1e30f; l_s[i] = 0.f; }

    float o[4][8];
#pragma unroll
    for (int i = 0; i < 4; i++)
#pragma unroll
        for (int j = 0; j < 8; j++) o[i][j] = 0.f;

    for (int kt = 0; kt < NKT; kt++) {
        __syncthreads();                /* prev tile fully consumed */
        /* load K (transposed+swizzled) and V (natural) */
        for (int i = tid; i < BKEYS * DH / 4; i += 256) {
            int key = i >> 4;
            int d   = (i & 15) << 2;
            const float* gp = K + base + (size_t)(kt * BKEYS + key) * HID + d;
            float4 k4 = *(const float4*)gp;
            Kt[att_swz(d + 0, key)] = k4.x;
            Kt[att_swz(d + 1, key)] = k4.y;
            Kt[att_swz(d + 2, key)] = k4.z;
            Kt[att_swz(d + 3, key)] = k4.w;
            float4 v4 = *(const float4*)(V + base + (size_t)(kt * BKEYS + key) * HID + d);
            *(float4*)&Vs[key * DH + d] = v4;
        }
        __syncthreads();

        /* ---- S = (Q/8) @ K^T  (8x8 micro) ---- */
        float s[8][8];
#pragma unroll
        for (int i = 0; i < 8; i++)
#pragma unroll
            for (int j = 0; j < 8; j++) s[i][j] = 0.f;

#pragma unroll 4
        for (int kk = 0; kk < DH; kk++) {
            int sw = ((kk >> 2) & 7) << 2;
            float a[8], bb[8];
            *(float4*)(a)      = *(const float4*)&Qt[kk * 128 + ((ty * 8)     ^ sw)];
            *(float4*)(a + 4)  = *(const float4*)&Qt[kk * 128 + ((ty * 8 + 4) ^ sw)];
            *(float4*)(bb)     = *(const float4*)&Kt[kk * 128 + ((tx * 8)     ^ sw)];
            *(float4*)(bb + 4) = *(const float4*)&Kt[kk * 128 + ((tx * 8 + 4) ^ sw)];
#pragma unroll
            for (int i = 0; i < 8; i++)
#pragma unroll
                for (int j = 0; j < 8; j++)
                    s[i][j] = fmaf(a[i], bb[j], s[i][j]);
        }

        /* ---- online softmax per row (row owned by one 16-lane group) ---- */
#pragma unroll
        for (int i = 0; i < 8; i++) {
            int row = ty * 8 + i;
            float mx = s[i][0];
#pragma unroll
            for (int j = 1; j < 8; j++) mx = fmaxf(mx, s[i][j]);
#pragma unroll
            for (int off = 8; off > 0; off >>= 1)
                mx = fmaxf(mx, __shfl_xor_sync(0xffffffffu, mx, off, 16));
            float m_old = m_s[row];
            float m_new = fmaxf(m_old, mx);
            float sum = 0.f;
#pragma unroll
            for (int j = 0; j < 8; j++) {
                float p = __expf(s[i][j] - m_new);
                s[i][j] = p;
                sum += p;
            }
#pragma unroll
            for (int off = 8; off > 0; off >>= 1)
                sum += __shfl_xor_sync(0xffffffffu, sum, off, 16);
            if (tx == 0) {
                float c = __expf(m_old - m_new);
                m_s[row] = m_new;
                l_s[row] = l_s[row] * c + sum;
                c_s[row] = c;
            }
            *(float4*)&Ps[row * PSP + tx * 8]     =
                make_float4(s[i][0], s[i][1], s[i][2], s[i][3]);
            *(float4*)&Ps[row * PSP + tx * 8 + 4] =
                make_float4(s[i][4], s[i][5], s[i][6], s[i][7]);
        }
        __syncthreads();

        /* ---- O = O*corr + P @ V  (4x8 micro) ---- */
#pragma unroll
        for (int i = 0; i < 4; i++) {
            float c = c_s[oty * 4 + i];
#pragma unroll
            for (int j = 0; j < 8; j++) o[i][j] *= c;
        }
#pragma unroll 4
        for (int kk = 0; kk < BKEYS; kk++) {
            float a0 = Ps[(oty * 4 + 0) * PSP + kk];
            float a1 = Ps[(oty * 4 + 1) * PSP + kk];
            float a2 = Ps[(oty * 4 + 2) * PSP + kk];
            float a3 = Ps[(oty * 4 + 3) * PSP + kk];
            float bb[8];
            *(float4*)(bb)     = *(const float4*)&Vs[kk * DH + otx * 8];
            *(float4*)(bb + 4) = *(const float4*)&Vs[kk * DH + otx * 8 + 4];
#pragma unroll
            for (int j = 0; j < 8; j++) {
                o[0][j] = fmaf(a0, bb[j], o[0][j]);
                o[1][j] = fmaf(a1, bb[j], o[1][j]);
                o[2][j] = fmaf(a2, bb[j], o[2][j]);
                o[3][j] = fmaf(a3, bb[j], o[3][j]);
            }
        }
    }

    /* normalize + write context (heads re-merge into [B,S,HID] layout) */
#pragma unroll
    for (int i = 0; i < 4; i++) {
        int row = oty * 4 + i;
        float inv = 1.0f / l_s[row];
        float* cp = C + base + (size_t)(qt * BQ + row) * HID + otx * 8;
        float4 r0, r1;
        r0.x = o[i][0] * inv; r0.y = o[i][1] * inv;
        r0.z = o[i][2] * inv; r0.w = o[i][3] * inv;
        r1.x = o[i][4] * inv; r1.y = o[i][5] * inv;
        r1.z = o[i][6] * inv; r1.w = o[i][7] * inv;
        *(float4*)cp       = r0;
        *(float4*)(cp + 4) = r1;
    }
}

/* ================= launch ================= */
extern "C" void kernel_launch(void* const* d_in, const int* in_sizes, int n_in,
                              void* d_out, int out_size)
{
    const float* q  = (const float*)d_in[0];
    const float* k  = (const float*)d_in[1];
    const float* v  = (const float*)d_in[2];
    const float* Wq = (const float*)d_in[3];
    const float* bq = (const float*)d_in[4];
    const float* Wk = (const float*)d_in[5];
    const float* bk = (const float*)d_in[6];
    const float* Wv = (const float*)d_in[7];
    const float* bv = (const float*)d_in[8];
    const float* Wo = (const float*)d_in[9];
    const float* bo = (const float*)d_in[10];
    float* out = (float*)d_out;

    float *gq, *gk, *gv, *gc;
    cudaGetSymbolAddress((void**)&gq, g_Q);
    cudaGetSymbolAddress((void**)&gk, g_K);
    cudaGetSymbolAddress((void**)&gv, g_V);
    cudaGetSymbolAddress((void**)&gc, g_C);

    cudaFuncSetAttribute((const void*)attn_kernel,
                         cudaFuncAttributeMaxDynamicSharedMemorySize,
                         ATTN_SMEM_BYTES);

    dim3 pg(MROWS / PM, HID / PN);      /* 64 x 4 */
    proj_gemm<<<pg, 256>>>(q, Wq, bq, gq, HID);
    proj_gemm<<<pg, 256>>>(k, Wk, bk, gk, HID);
    proj_gemm<<<pg, 256>>>(v, Wv, bv, gv, HID);

    dim3 ag(S_LEN / BQ, NHEAD, BATCH);  /* 32 x 8 x 2 */
    attn_kernel<<<ag, 256, ATTN_SMEM_BYTES>>>(gq, gk, gv, gc);

    proj_gemm<<<pg, 256>>>(gc, Wo, bo, out, HID);
}

// round 9
// speedup vs baseline: 2.5109x; 2.5109x over previous
#include <cuda_runtime.h>
#include <cstdint>

#define HID   512
#define S_LEN 4096
#define BATCH 2
#define NHEAD 8
#define DH    64
#define MROWS (BATCH * S_LEN)   /* 8192 */

/* -------- scratch (no allocations allowed) -------- */
__device__ float g_Q[MROWS * HID];
__device__ float g_K[MROWS * HID];
__device__ float g_V[MROWS * HID];
__device__ float g_C[MROWS * HID];

/* ================= projection GEMM : Y = X @ W^T + b =================
 * X: [M,K] row-major, W: [N,K] row-major (nn.Linear weight), Y: [M,512]
 * 128x128 tile, BK=8, 256 threads, 8x8 micro-tile. (fp32, proven) */
#define PM 128
#define PN 128
#define PK 8

__global__ void __launch_bounds__(256, 2) proj_gemm(
    const float* __restrict__ X, const float* __restrict__ W,
    const float* __restrict__ bias, float* __restrict__ Y, int Kdim)
{
    __shared__ float As[PK][PM];
    __shared__ float Bs[PK][PN];

    const int tid = threadIdx.x;
    const int tx = tid & 15;
    const int ty = tid >> 4;
    const int bm = blockIdx.x * PM;
    const int bn = blockIdx.y * PN;

    const int lrow = tid >> 1;
    const int lcol = (tid & 1) * 4;

    const float* Ap = X + (size_t)(bm + lrow) * Kdim + lcol;
    const float* Bp = W + (size_t)(bn + lrow) * Kdim + lcol;

    float acc[8][8];
#pragma unroll
    for (int i = 0; i < 8; i++)
#pragma unroll
        for (int j = 0; j < 8; j++) acc[i][j] = 0.f;

    for (int k0 = 0; k0 < Kdim; k0 += PK) {
        float4 a4 = *(const float4*)(Ap + k0);
        float4 b4 = *(const float4*)(Bp + k0);
        __syncthreads();
        As[lcol + 0][lrow] = a4.x;
        As[lcol + 1][lrow] = a4.y;
        As[lcol + 2][lrow] = a4.z;
        As[lcol + 3][lrow] = a4.w;
        Bs[lcol + 0][lrow] = b4.x;
        Bs[lcol + 1][lrow] = b4.y;
        Bs[lcol + 2][lrow] = b4.z;
        Bs[lcol + 3][lrow] = b4.w;
        __syncthreads();
#pragma unroll
        for (int kk = 0; kk < PK; kk++) {
            float a[8], b[8];
            *(float4*)(a)     = *(const float4*)&As[kk][ty * 8];
            *(float4*)(a + 4) = *(const float4*)&As[kk][ty * 8 + 4];
            *(float4*)(b)     = *(const float4*)&Bs[kk][tx * 8];
            *(float4*)(b + 4) = *(const float4*)&Bs[kk][tx * 8 + 4];
#pragma unroll
            for (int i = 0; i < 8; i++)
#pragma unroll
                for (int j = 0; j < 8; j++)
                    acc[i][j] = fmaf(a[i], b[j], acc[i][j]);
        }
    }

    float bv[8];
#pragma unroll
    for (int j = 0; j < 8; j++) bv[j] = bias[bn + tx * 8 + j];

#pragma unroll
    for (int i = 0; i < 8; i++) {
        int row = bm + ty * 8 + i;
        float* yp = Y + (size_t)row * HID + bn + tx * 8;
        float4 r0, r1;
        r0.x = acc[i][0] + bv[0]; r0.y = acc[i][1] + bv[1];
        r0.z = acc[i][2] + bv[2]; r0.w = acc[i][3] + bv[3];
        r1.x = acc[i][4] + bv[4]; r1.y = acc[i][5] + bv[5];
        r1.z = acc[i][6] + bv[6]; r1.w = acc[i][7] + bv[7];
        *(float4*)yp       = r0;
        *(float4*)(yp + 4) = r1;
    }
}

/* ================= flash attention (tf32 tensor cores) =================
 * CTA: 128 q rows x 128 keys per tile, 8 warps, 256 threads.
 * Warp w owns q-rows 16w..16w+15 for BOTH QK^T and PV -> softmax state
 * (m, l, correction) lives in registers; P tile is warp-private in smem.
 * mma.sync.aligned.m16n8k8.row.col.f32.tf32.tf32.f32 */
#define BQ    128
#define BKEYS 128
#define NKT   (S_LEN / BKEYS)

#define QK_PITCH 68      /* banks: 4g+q  -> conflict-free frag loads */
#define V_PITCH  72      /* banks: 8q+8n+g -> conflict-free */
#define P_PITCH  132     /* banks: 4g+8ks+q -> conflict-free loads */

#define ATTN_SMEM_FLOATS (BQ*QK_PITCH + BKEYS*QK_PITCH + BKEYS*V_PITCH + BQ*P_PITCH)
#define ATTN_SMEM_BYTES  (ATTN_SMEM_FLOATS * 4)

/* Q pre-scale: 1/sqrt(64) * log2(e)  (softmax done in base 2) */
#define QSCALE 0.1803368801111244f

__device__ __forceinline__ uint32_t tf32_rna(float x) {
    uint32_t y;
    asm("cvt.rna.tf32.f32 %0, %1;" : "=r"(y) : "f"(x));
    return y;
}

__device__ __forceinline__ float ex2(float x) {
    float y;
    asm("ex2.approx.ftz.f32 %0, %1;" : "=f"(y) : "f"(x));
    return y;
}

__device__ __forceinline__ void mma_tf32(float4& c,
    uint32_t a0, uint32_t a1, uint32_t a2, uint32_t a3,
    uint32_t b0, uint32_t b1)
{
    asm volatile(
        "mma.sync.aligned.m16n8k8.row.col.f32.tf32.tf32.f32 "
        "{%0,%1,%2,%3}, {%4,%5,%6,%7}, {%8,%9}, {%0,%1,%2,%3};\n"
        : "+f"(c.x), "+f"(c.y), "+f"(c.z), "+f"(c.w)
        : "r"(a0), "r"(a1), "r"(a2), "r"(a3), "r"(b0), "r"(b1));
}

__global__ void __launch_bounds__(256, 1) attn_kernel(
    const float* __restrict__ Q, const float* __restrict__ K,
    const float* __restrict__ V, float* __restrict__ C)
{
    extern __shared__ float sm[];
    float* Qs = sm;                          /* [128][68] tf32 bits, pre-scaled */
    float* Ks = Qs + BQ * QK_PITCH;          /* [128][68] tf32 bits */
    float* Vs = Ks + BKEYS * QK_PITCH;       /* [128][72] tf32 bits */
    float* Ps = Vs + BKEYS * V_PITCH;        /* [128][132] tf32 bits */

    const int tid  = threadIdx.x;
    const int w    = tid >> 5;         /* warp 0..7 */
    const int lane = tid & 31;
    const int g    = lane >> 2;        /* group 0..7 (row within frag) */
    const int q    = lane & 3;         /* thread-in-group (col within frag) */

    const int qt = blockIdx.x, h = blockIdx.y, b = blockIdx.z;
    const size_t base = (size_t)b * S_LEN * HID + h * DH;

    /* ---- load Q tile (pre-scaled, tf32) ---- */
    for (int i = tid; i < BQ * DH / 4; i += 256) {
        int row = i >> 4;
        int d   = (i & 15) << 2;
        float4 q4 = *(const float4*)(Q + base + (size_t)(qt * BQ + row) * HID + d);
        uint4 qb = make_uint4(tf32_rna(q4.x * QSCALE), tf32_rna(q4.y * QSCALE),
                              tf32_rna(q4.z * QSCALE), tf32_rna(q4.w * QSCALE));
        *(uint4*)&Qs[row * QK_PITCH + d] = qb;
    }

    float m0 = -1e30f, m1 = -1e30f;
    float l0 = 0.f,    l1 = 0.f;
    float4 o[8];
#pragma unroll
    for (int n = 0; n < 8; n++) o[n] = make_float4(0.f, 0.f, 0.f, 0.f);

    const float* qrow0 = Qs + (16 * w + g) * QK_PITCH;   /* row g of warp tile */
    float* prow0 = Ps + (16 * w + g) * P_PITCH;
    float* prow1 = prow0 + 8 * P_PITCH;

    for (int kt = 0; kt < NKT; kt++) {
        __syncthreads();   /* everyone done reading Ks/Vs of prev tile */

        /* ---- load K, V tiles (tf32) ---- */
        for (int i = tid; i < BKEYS * DH / 4; i += 256) {
            int key = i >> 4;
            int d   = (i & 15) << 2;
            const float* gk = K + base + (size_t)(kt * BKEYS + key) * HID + d;
            float4 k4 = *(const float4*)gk;
            uint4 kb = make_uint4(tf32_rna(k4.x), tf32_rna(k4.y),
                                  tf32_rna(k4.z), tf32_rna(k4.w));
            *(uint4*)&Ks[key * QK_PITCH + d] = kb;
            float4 v4 = *(const float4*)(V + base + (size_t)(kt * BKEYS + key) * HID + d);
            uint4 vb = make_uint4(tf32_rna(v4.x), tf32_rna(v4.y),
                                  tf32_rna(v4.z), tf32_rna(v4.w));
            *(uint4*)&Vs[key * V_PITCH + d] = vb;
        }
        __syncthreads();

        /* ---- S = Qs @ Ks^T : warp computes 16 rows x 128 keys ---- */
        float4 sa[16];
#pragma unroll
        for (int n = 0; n < 16; n++) sa[n] = make_float4(0.f, 0.f, 0.f, 0.f);

#pragma unroll
        for (int ks = 0; ks < 8; ks++) {
            int c = ks * 8 + q;
            uint32_t a0 = __float_as_uint(qrow0[c]);
            uint32_t a1 = __float_as_uint(qrow0[8 * QK_PITCH + c]);
            uint32_t a2 = __float_as_uint(qrow0[c + 4]);
            uint32_t a3 = __float_as_uint(qrow0[8 * QK_PITCH + c + 4]);
#pragma unroll
            for (int n = 0; n < 16; n++) {
                const float* kb = Ks + (8 * n + g) * QK_PITCH + c;
                uint32_t b0 = __float_as_uint(kb[0]);
                uint32_t b1 = __float_as_uint(kb[4]);
                mma_tf32(sa[n], a0, a1, a2, a3, b0, b1);
            }
        }

        /* ---- online softmax (base-2, state in registers) ----
         * row0 = 16w+g (sa.x/.y), row1 = 16w+g+8 (sa.z/.w) */
        float mx0 = -1e30f, mx1 = -1e30f;
#pragma unroll
        for (int n = 0; n < 16; n++) {
            mx0 = fmaxf(mx0, fmaxf(sa[n].x, sa[n].y));
            mx1 = fmaxf(mx1, fmaxf(sa[n].z, sa[n].w));
        }
        mx0 = fmaxf(mx0, __shfl_xor_sync(0xffffffffu, mx0, 1));
        mx0 = fmaxf(mx0, __shfl_xor_sync(0xffffffffu, mx0, 2));
        mx1 = fmaxf(mx1, __shfl_xor_sync(0xffffffffu, mx1, 1));
        mx1 = fmaxf(mx1, __shfl_xor_sync(0xffffffffu, mx1, 2));

        float mn0 = fmaxf(m0, mx0), mn1 = fmaxf(m1, mx1);
        float cr0 = ex2(m0 - mn0),  cr1 = ex2(m1 - mn1);
        m0 = mn0; m1 = mn1;

        float s0 = 0.f, s1 = 0.f;
#pragma unroll
        for (int n = 0; n < 16; n++) {
            float px = ex2(sa[n].x - m0), py = ex2(sa[n].y - m0);
            float pz = ex2(sa[n].z - m1), pw = ex2(sa[n].w - m1);
            s0 += px + py;
            s1 += pz + pw;
            float2 t0 = make_float2(__uint_as_float(tf32_rna(px)),
                                    __uint_as_float(tf32_rna(py)));
            float2 t1 = make_float2(__uint_as_float(tf32_rna(pz)),
                                    __uint_as_float(tf32_rna(pw)));
            *(float2*)&prow0[8 * n + 2 * q] = t0;
            *(float2*)&prow1[8 * n + 2 * q] = t1;
        }
        s0 += __shfl_xor_sync(0xffffffffu, s0, 1);
        s0 += __shfl_xor_sync(0xffffffffu, s0, 2);
        s1 += __shfl_xor_sync(0xffffffffu, s1, 1);
        s1 += __shfl_xor_sync(0xffffffffu, s1, 2);
        l0 = l0 * cr0 + s0;
        l1 = l1 * cr1 + s1;

#pragma unroll
        for (int n = 0; n < 8; n++) {
            o[n].x *= cr0; o[n].y *= cr0;
            o[n].z *= cr1; o[n].w *= cr1;
        }
        __syncwarp();   /* P rows are warp-private; order stores vs loads */

        /* ---- O += P @ V : 16 rows x 64 cols per warp ---- */
#pragma unroll
        for (int ks = 0; ks < 16; ks++) {
            int kc = ks * 8 + q;
            uint32_t a0 = __float_as_uint(prow0[kc]);
            uint32_t a1 = __float_as_uint(prow1[kc]);
            uint32_t a2 = __float_as_uint(prow0[kc + 4]);
            uint32_t a3 = __float_as_uint(prow1[kc + 4]);
            const float* vb0 = Vs + kc * V_PITCH + g;
            const float* vb1 = Vs + (kc + 4) * V_PITCH + g;
#pragma unroll
            for (int n = 0; n < 8; n++) {
                uint32_t b0 = __float_as_uint(vb0[8 * n]);
                uint32_t b1 = __float_as_uint(vb1[8 * n]);
                mma_tf32(o[n], a0, a1, a2, a3, b0, b1);
            }
        }
    }

    /* ---- normalize + write context ---- */
    float inv0 = 1.0f / l0;
    float inv1 = 1.0f / l1;
    int grow = qt * BQ + 16 * w + g;
    float* cp0 = C + base + (size_t)grow * HID;
    float* cp1 = cp0 + (size_t)8 * HID;
#pragma unroll
    for (int n = 0; n < 8; n++) {
        *(float2*)&cp0[8 * n + 2 * q] = make_float2(o[n].x * inv0, o[n].y * inv0);
        *(float2*)&cp1[8 * n + 2 * q] = make_float2(o[n].z * inv1, o[n].w * inv1);
    }
}

/* ================= launch ================= */
extern "C" void kernel_launch(void* const* d_in, const int* in_sizes, int n_in,
                              void* d_out, int out_size)
{
    const float* q  = (const float*)d_in[0];
    const float* k  = (const float*)d_in[1];
    const float* v  = (const float*)d_in[2];
    const float* Wq = (const float*)d_in[3];
    const float* bq = (const float*)d_in[4];
    const float* Wk = (const float*)d_in[5];
    const float* bk = (const float*)d_in[6];
    const float* Wv = (const float*)d_in[7];
    const float* bv = (const float*)d_in[8];
    const float* Wo = (const float*)d_in[9];
    const float* bo = (const float*)d_in[10];
    float* out = (float*)d_out;

    float *gq, *gk, *gv, *gc;
    cudaGetSymbolAddress((void**)&gq, g_Q);
    cudaGetSymbolAddress((void**)&gk, g_K);
    cudaGetSymbolAddress((void**)&gv, g_V);
    cudaGetSymbolAddress((void**)&gc, g_C);

    cudaFuncSetAttribute((const void*)attn_kernel,
                         cudaFuncAttributeMaxDynamicSharedMemorySize,
                         ATTN_SMEM_BYTES);

    dim3 pg(MROWS / PM, HID / PN);      /* 64 x 4 */
    proj_gemm<<<pg, 256>>>(q, Wq, bq, gq, HID);
    proj_gemm<<<pg, 256>>>(k, Wk, bk, gk, HID);
    proj_gemm<<<pg, 256>>>(v, Wv, bv, gv, HID);

    dim3 ag(S_LEN / BQ, NHEAD, BATCH);  /* 32 x 8 x 2 */
    attn_kernel<<<ag, 256, ATTN_SMEM_BYTES>>>(gq, gk, gv, gc);

    proj_gemm<<<pg, 256>>>(gc, Wo, bo, out, HID);
}

// round 10
// speedup vs baseline: 8.5121x; 3.3901x over previous
#include <cuda_runtime.h>
#include <cuda_fp16.h>
#include <cstdint>

#define HID   512
#define S_LEN 4096
#define BATCH 2
#define NHEAD 8
#define DH    64
#define MROWS (BATCH * S_LEN)   /* 8192 */

/* -------- scratch (no allocations allowed) -------- */
__device__ __half g_Q[MROWS * HID];
__device__ __half g_K[MROWS * HID];
__device__ __half g_V[MROWS * HID];
__device__ __half g_C[MROWS * HID];

/* Q pre-scale: 1/sqrt(64) * log2(e)  (softmax done in base 2) */
#define QSCALE 0.1803368801111244f

/* ---------------- common helpers ---------------- */
__device__ __forceinline__ float ex2(float x) {
    float y;
    asm("ex2.approx.ftz.f32 %0, %1;" : "=f"(y) : "f"(x));
    return y;
}

__device__ __forceinline__ uint32_t h2pack(float lo, float hi) {
    __half2 h = __floats2half2_rn(lo, hi);
    return reinterpret_cast<uint32_t&>(h);
}

__device__ __forceinline__ void mma_f16(float4& c,
    uint32_t a0, uint32_t a1, uint32_t a2, uint32_t a3,
    uint32_t b0, uint32_t b1)
{
    asm volatile(
        "mma.sync.aligned.m16n8k16.row.col.f32.f16.f16.f32 "
        "{%0,%1,%2,%3}, {%4,%5,%6,%7}, {%8,%9}, {%0,%1,%2,%3};\n"
        : "+f"(c.x), "+f"(c.y), "+f"(c.z), "+f"(c.w)
        : "r"(a0), "r"(a1), "r"(a2), "r"(a3), "r"(b0), "r"(b1));
}

__device__ __forceinline__ void ldsm_x4(uint32_t* r, const __half* p) {
    uint32_t a = (uint32_t)__cvta_generic_to_shared(p);
    asm volatile("ldmatrix.sync.aligned.m8n8.x4.shared.b16 {%0,%1,%2,%3}, [%4];"
        : "=r"(r[0]), "=r"(r[1]), "=r"(r[2]), "=r"(r[3]) : "r"(a));
}

__device__ __forceinline__ void ldsm_x4_t(uint32_t* r, const __half* p) {
    uint32_t a = (uint32_t)__cvta_generic_to_shared(p);
    asm volatile("ldmatrix.sync.aligned.m8n8.x4.trans.shared.b16 {%0,%1,%2,%3}, [%4];"
        : "=r"(r[0]), "=r"(r[1]), "=r"(r[2]), "=r"(r[3]) : "r"(a));
}

/* swizzled address in a [rows][64] half tile: 16B chunks XORed by row&7 */
__device__ __forceinline__ __half* swz(__half* base, int row, int dch) {
    return base + row * 64 + ((dch ^ (row & 7)) << 3);
}

/* ================= projection GEMM : Y = X @ W^T + b =================
 * fp16 tensor cores (m16n8k16 + ldmatrix). CTA tile 128x128, BK=64,
 * 8 warps in 4(m) x 2(n); warp tile 32x64. X: [M,512], W: [N,512].
 * IN_HALF: X is half (g_C); else fp32 (harness inputs).
 * OUT_HALF: Y is half (scratch); else fp32 (d_out). W, bias always fp32. */
template<bool IN_HALF, bool OUT_HALF>
__global__ void __launch_bounds__(256, 2) proj_mma(
    const void* __restrict__ Xv, const float* __restrict__ W,
    const float* __restrict__ bias, void* __restrict__ Yv)
{
    __shared__ __align__(16) __half Xs[128 * 64];
    __shared__ __align__(16) __half Ws[128 * 64];

    const int tid  = threadIdx.x;
    const int w    = tid >> 5;
    const int lane = tid & 31;
    const int g    = lane >> 2;
    const int q    = lane & 3;
    const int mi   = lane >> 3;
    const int r8   = lane & 7;
    const int wm   = w >> 1;       /* 0..3 */
    const int wn   = w & 1;        /* 0..1 */
    const int bm   = blockIdx.x * 128;
    const int bn   = blockIdx.y * 128;

    float4 acc[2][8];
#pragma unroll
    for (int i = 0; i < 2; i++)
#pragma unroll
        for (int j = 0; j < 8; j++) acc[i][j] = make_float4(0.f, 0.f, 0.f, 0.f);

    for (int k0 = 0; k0 < HID; k0 += 64) {
        __syncthreads();
        /* fill Xs, Ws (1024 16B chunks each; 4 per thread) */
#pragma unroll
        for (int jj = 0; jj < 4; jj++) {
            int i = tid + jj * 256;
            int row = i >> 3, c = i & 7;
            uint4 hx;
            if (IN_HALF) {
                hx = *(const uint4*)((const __half*)Xv +
                        (size_t)(bm + row) * HID + k0 + c * 8);
            } else {
                const float* gp = (const float*)Xv +
                        (size_t)(bm + row) * HID + k0 + c * 8;
                float4 f0 = *(const float4*)gp;
                float4 f1 = *(const float4*)(gp + 4);
                hx.x = h2pack(f0.x, f0.y); hx.y = h2pack(f0.z, f0.w);
                hx.z = h2pack(f1.x, f1.y); hx.w = h2pack(f1.z, f1.w);
            }
            *(uint4*)swz(Xs, row, c) = hx;

            const float* wp = W + (size_t)(bn + row) * HID + k0 + c * 8;
            float4 w0 = *(const float4*)wp;
            float4 w1 = *(const float4*)(wp + 4);
            uint4 hw;
            hw.x = h2pack(w0.x, w0.y); hw.y = h2pack(w0.z, w0.w);
            hw.z = h2pack(w1.x, w1.y); hw.w = h2pack(w1.z, w1.w);
            *(uint4*)swz(Ws, row, c) = hw;
        }
        __syncthreads();

#pragma unroll
        for (int kc = 0; kc < 4; kc++) {
            uint32_t a0[4], a1[4];
            {
                int row = 32 * wm + r8 + ((mi & 1) << 3);
                int dch = 2 * kc + ((mi >> 1) & 1);
                ldsm_x4(a0, swz(Xs, row, dch));
                ldsm_x4(a1, swz(Xs, row + 16, dch));
            }
#pragma unroll
            for (int np = 0; np < 4; np++) {
                uint32_t b[4];
                int nrow = 64 * wn + 16 * np + r8 + (((mi >> 1) & 1) << 3);
                int dch  = 2 * kc + (mi & 1);
                ldsm_x4(b, swz(Ws, nrow, dch));
                mma_f16(acc[0][2*np],   a0[0], a0[1], a0[2], a0[3], b[0], b[1]);
                mma_f16(acc[0][2*np+1], a0[0], a0[1], a0[2], a0[3], b[2], b[3]);
                mma_f16(acc[1][2*np],   a1[0], a1[1], a1[2], a1[3], b[0], b[1]);
                mma_f16(acc[1][2*np+1], a1[0], a1[1], a1[2], a1[3], b[2], b[3]);
            }
        }
    }

    /* epilogue: + bias, store */
#pragma unroll
    for (int mi2 = 0; mi2 < 2; mi2++) {
#pragma unroll
        for (int nt = 0; nt < 8; nt++) {
            int col = bn + 64 * wn + 8 * nt + 2 * q;
            float2 bv = *(const float2*)&bias[col];
            float4 c = acc[mi2][nt];
            int row0 = bm + 32 * wm + 16 * mi2 + g;
            float x0 = c.x + bv.x, y0 = c.y + bv.y;
            float x1 = c.z + bv.x, y1 = c.w + bv.y;
            if (OUT_HALF) {
                __half* Y = (__half*)Yv;
                *(uint32_t*)&Y[(size_t)row0 * HID + col]       = h2pack(x0, y0);
                *(uint32_t*)&Y[(size_t)(row0 + 8) * HID + col] = h2pack(x1, y1);
            } else {
                float* Y = (float*)Yv;
                *(float2*)&Y[(size_t)row0 * HID + col]       = make_float2(x0, y0);
                *(float2*)&Y[(size_t)(row0 + 8) * HID + col] = make_float2(x1, y1);
            }
        }
    }
}

/* ================= flash attention (fp16 tensor cores) =================
 * CTA: 128 q rows x 128 keys/tile, 8 warps; warp w owns q-rows 16w..16w+15
 * for both QK^T and PV. P never touches smem: the m16n8k16 C fragment of S
 * is bit-layout-identical to the A fragment of P@V (FA-2 trick).
 * K/V gmem loads are register double-buffered across tiles. */
#define BQ    128
#define BKEYS 128
#define NKT   (S_LEN / BKEYS)

#define ATTN_SMEM_BYTES (3 * 128 * 64 * 2)   /* Qs + Ks + Vs, 48KB */

__global__ void __launch_bounds__(256) attn_kernel(
    const __half* __restrict__ Q, const __half* __restrict__ K,
    const __half* __restrict__ V, __half* __restrict__ C)
{
    extern __shared__ __half smh[];
    __half* Qs = smh;                /* [128][64] swizzled, pre-scaled */
    __half* Ks = Qs + 128 * 64;
    __half* Vs = Ks + 128 * 64;

    const int tid  = threadIdx.x;
    const int w    = tid >> 5;
    const int lane = tid & 31;
    const int g    = lane >> 2;
    const int q    = lane & 3;
    const int mi   = lane >> 3;
    const int r8   = lane & 7;

    const int qt = blockIdx.x, h = blockIdx.y, b = blockIdx.z;
    const size_t base = (size_t)b * S_LEN * HID + h * DH;

    /* ---- fill Q (scaled) ---- */
    const __half2 qsc = __float2half2_rn(QSCALE);
#pragma unroll
    for (int jj = 0; jj < 4; jj++) {
        int i = tid + jj * 256;
        int row = i >> 3, c = i & 7;
        uint4 v = *(const uint4*)(Q + base + (size_t)(qt * BQ + row) * HID + c * 8);
        __half2* hp = (__half2*)&v;
        hp[0] = __hmul2(hp[0], qsc); hp[1] = __hmul2(hp[1], qsc);
        hp[2] = __hmul2(hp[2], qsc); hp[3] = __hmul2(hp[3], qsc);
        *(uint4*)swz(Qs, row, c) = v;
    }

    /* prefetch tile 0 of K/V into registers */
    uint4 kreg[4], vreg[4];
#pragma unroll
    for (int jj = 0; jj < 4; jj++) {
        int i = tid + jj * 256;
        int row = i >> 3, c = i & 7;
        kreg[jj] = *(const uint4*)(K + base + (size_t)row * HID + c * 8);
        vreg[jj] = *(const uint4*)(V + base + (size_t)row * HID + c * 8);
    }
    __syncthreads();

    /* ---- Q fragments: persist across all key tiles ---- */
    uint32_t qa[4][4];
#pragma unroll
    for (int kc = 0; kc < 4; kc++) {
        int row = 16 * w + r8 + ((mi & 1) << 3);
        int dch = 2 * kc + ((mi >> 1) & 1);
        ldsm_x4(qa[kc], swz(Qs, row, dch));
    }

    float m0 = -1e30f, m1 = -1e30f;
    float l0 = 0.f,    l1 = 0.f;
    float4 o[8];
#pragma unroll
    for (int n = 0; n < 8; n++) o[n] = make_float4(0.f, 0.f, 0.f, 0.f);

    for (int kt = 0; kt < NKT; kt++) {
        __syncthreads();               /* prev tile fully consumed */
#pragma unroll
        for (int jj = 0; jj < 4; jj++) {
            int i = tid + jj * 256;
            int row = i >> 3, c = i & 7;
            *(uint4*)swz(Ks, row, c) = kreg[jj];
            *(uint4*)swz(Vs, row, c) = vreg[jj];
        }
        __syncthreads();
        if (kt + 1 < NKT) {            /* overlap next gmem load with compute */
#pragma unroll
            for (int jj = 0; jj < 4; jj++) {
                int i = tid + jj * 256;
                int row = i >> 3, c = i & 7;
                const size_t off = base + (size_t)((kt + 1) * BKEYS + row) * HID + c * 8;
                kreg[jj] = *(const uint4*)(K + off);
                vreg[jj] = *(const uint4*)(V + off);
            }
        }

        /* ---- S = Qs @ Ks^T : 16 rows x 128 keys per warp ---- */
        float4 sa[16];
#pragma unroll
        for (int n = 0; n < 16; n++) sa[n] = make_float4(0.f, 0.f, 0.f, 0.f);

#pragma unroll
        for (int np = 0; np < 8; np++) {
#pragma unroll
            for (int kc = 0; kc < 4; kc++) {
                uint32_t kb[4];
                int key = 16 * np + r8 + (((mi >> 1) & 1) << 3);
                int dch = 2 * kc + (mi & 1);
                ldsm_x4(kb, swz(Ks, key, dch));
                mma_f16(sa[2*np],   qa[kc][0], qa[kc][1], qa[kc][2], qa[kc][3], kb[0], kb[1]);
                mma_f16(sa[2*np+1], qa[kc][0], qa[kc][1], qa[kc][2], qa[kc][3], kb[2], kb[3]);
            }
        }

        /* ---- online softmax (base-2); P -> half2 regs, no smem ---- */
        float mx0 = -1e30f, mx1 = -1e30f;
#pragma unroll
        for (int n = 0; n < 16; n++) {
            mx0 = fmaxf(mx0, fmaxf(sa[n].x, sa[n].y));
            mx1 = fmaxf(mx1, fmaxf(sa[n].z, sa[n].w));
        }
        mx0 = fmaxf(mx0, __shfl_xor_sync(0xffffffffu, mx0, 1));
        mx0 = fmaxf(mx0, __shfl_xor_sync(0xffffffffu, mx0, 2));
        mx1 = fmaxf(mx1, __shfl_xor_sync(0xffffffffu, mx1, 1));
        mx1 = fmaxf(mx1, __shfl_xor_sync(0xffffffffu, mx1, 2));

        float mn0 = fmaxf(m0, mx0), mn1 = fmaxf(m1, mx1);
        float cr0 = ex2(m0 - mn0),  cr1 = ex2(m1 - mn1);
        m0 = mn0; m1 = mn1;

        uint32_t pa[16][2];
        float s0 = 0.f, s1 = 0.f;
#pragma unroll
        for (int n = 0; n < 16; n++) {
            float px = ex2(sa[n].x - m0), py = ex2(sa[n].y - m0);
            float pz = ex2(sa[n].z - m1), pw = ex2(sa[n].w - m1);
            s0 += px + py;
            s1 += pz + pw;
            pa[n][0] = h2pack(px, py);
            pa[n][1] = h2pack(pz, pw);
        }
        s0 += __shfl_xor_sync(0xffffffffu, s0, 1);
        s0 += __shfl_xor_sync(0xffffffffu, s0, 2);
        s1 += __shfl_xor_sync(0xffffffffu, s1, 1);
        s1 += __shfl_xor_sync(0xffffffffu, s1, 2);
        l0 = l0 * cr0 + s0;
        l1 = l1 * cr1 + s1;

#pragma unroll
        for (int n = 0; n < 8; n++) {
            o[n].x *= cr0; o[n].y *= cr0;
            o[n].z *= cr1; o[n].w *= cr1;
        }

        /* ---- O += P @ V : A frags straight from registers ---- */
#pragma unroll
        for (int m = 0; m < 8; m++) {
            uint32_t a0 = pa[2*m][0],   a1 = pa[2*m][1];
            uint32_t a2 = pa[2*m+1][0], a3 = pa[2*m+1][1];
#pragma unroll
            for (int jp = 0; jp < 4; jp++) {
                uint32_t vb[4];
                int key = 16 * m + r8 + ((mi & 1) << 3);
                int dch = 2 * jp + ((mi >> 1) & 1);
                ldsm_x4_t(vb, swz(Vs, key, dch));
                mma_f16(o[2*jp],   a0, a1, a2, a3, vb[0], vb[1]);
                mma_f16(o[2*jp+1], a0, a1, a2, a3, vb[2], vb[3]);
            }
        }
    }

    /* ---- normalize + write context (half) ---- */
    float inv0 = 1.0f / l0;
    float inv1 = 1.0f / l1;
    int grow = qt * BQ + 16 * w + g;
    __half* cp0 = C + base + (size_t)grow * HID;
    __half* cp1 = cp0 + (size_t)8 * HID;
#pragma unroll
    for (int n = 0; n < 8; n++) {
        *(uint32_t*)&cp0[8 * n + 2 * q] = h2pack(o[n].x * inv0, o[n].y * inv0);
        *(uint32_t*)&cp1[8 * n + 2 * q] = h2pack(o[n].z * inv1, o[n].w * inv1);
    }
}

/* ================= launch ================= */
extern "C" void kernel_launch(void* const* d_in, const int* in_sizes, int n_in,
                              void* d_out, int out_size)
{
    const float* q  = (const float*)d_in[0];
    const float* k  = (const float*)d_in[1];
    const float* v  = (const float*)d_in[2];
    const float* Wq = (const float*)d_in[3];
    const float* bq = (const float*)d_in[4];
    const float* Wk = (const float*)d_in[5];
    const float* bk = (const float*)d_in[6];
    const float* Wv = (const float*)d_in[7];
    const float* bv = (const float*)d_in[8];
    const float* Wo = (const float*)d_in[9];
    const float* bo = (const float*)d_in[10];
    float* out = (float*)d_out;

    __half *gq, *gk, *gv, *gc;
    cudaGetSymbolAddress((void**)&gq, g_Q);
    cudaGetSymbolAddress((void**)&gk, g_K);
    cudaGetSymbolAddress((void**)&gv, g_V);
    cudaGetSymbolAddress((void**)&gc, g_C);

    cudaFuncSetAttribute((const void*)attn_kernel,
                         cudaFuncAttributeMaxDynamicSharedMemorySize,
                         ATTN_SMEM_BYTES);

    dim3 pg(MROWS / 128, HID / 128);    /* 64 x 4 */
    proj_mma<false, true><<<pg, 256>>>(q, Wq, bq, gq);
    proj_mma<false, true><<<pg, 256>>>(k, Wk, bk, gk);
    proj_mma<false, true><<<pg, 256>>>(v, Wv, bv, gv);

    dim3 ag(S_LEN / BQ, NHEAD, BATCH);  /* 32 x 8 x 2 */
    attn_kernel<<<ag, 256, ATTN_SMEM_BYTES>>>(gq, gk, gv, gc);

    proj_mma<true, false><<<pg, 256>>>(gc, Wo, bo, out);
}